// round 2
// baseline (speedup 1.0000x reference)
#include <cuda_runtime.h>
#include <math.h>

// Problem constants
#define Bq   8
#define Sq   1024
#define Dq   512
#define Hq   8
#define DHq  64
#define BSr  (Bq*Sq)        // 8192 rows
#define BSD  (Bq*Sq*Dq)     // 4194304 elements

typedef unsigned long long u64;

// ---------------- packed f32x2 helpers ----------------
__device__ __forceinline__ u64 dup2(float x) {
    u64 r; asm("mov.b64 %0, {%1,%1};" : "=l"(r) : "f"(x)); return r;
}
__device__ __forceinline__ u64 ffma2(u64 a, u64 b, u64 c) {
    u64 d; asm("fma.rn.f32x2 %0, %1, %2, %3;" : "=l"(d) : "l"(a), "l"(b), "l"(c)); return d;
}
__device__ __forceinline__ u64 fmul2(u64 a, u64 b) {
    u64 d; asm("mul.rn.f32x2 %0, %1, %2;" : "=l"(d) : "l"(a), "l"(b)); return d;
}
__device__ __forceinline__ float2 unpk(u64 v) {
    float2 f; asm("mov.b64 {%0,%1}, %2;" : "=f"(f.x), "=f"(f.y) : "l"(v)); return f;
}

// ---------------- device scratch (no allocations allowed) ----------------
__device__ float g_E [BSD];  // enc_in
__device__ float g_DI[BSD];  // dec_in
__device__ float g_Q [BSD];
__device__ float g_K [BSD];
__device__ float g_V [BSD];
__device__ float g_S [BSD];  // attention output
__device__ float g_I [BSD];  // inter / i2
__device__ float g_EO[BSD];  // enc_out

// ---------------- positional-embedding add ----------------
__global__ void __launch_bounds__(256) add_pos_kernel(const float* __restrict__ x,
                                                      float* __restrict__ out) {
    int idx = blockIdx.x * 256 + threadIdx.x;
    int d = idx & (Dq - 1);
    int s = (idx >> 9) & (Sq - 1);
    float freq  = expf((float)d * -0.0359778920794f);
    float angle = (float)s * freq;
    float pe = (d & 1) ? cosf(angle) : sinf(angle);
    out[idx] = x[idx] + pe;
}

// ---------------- fused LayerNorm + residual ----------------
__global__ void __launch_bounds__(256) ln_add_kernel(const float* __restrict__ x,
                                                     const float* __restrict__ gamma,
                                                     const float* __restrict__ beta,
                                                     const float* __restrict__ basep,
                                                     float scale,
                                                     float* __restrict__ out) {
    __shared__ float red[256];
    int t = threadIdx.x;
    size_t off = (size_t)blockIdx.x * Dq;

    float v0 = x[off + t];
    float v1 = x[off + t + 256];

    red[t] = v0 + v1;
    __syncthreads();
    #pragma unroll
    for (int s2 = 128; s2 > 0; s2 >>= 1) {
        if (t < s2) red[t] += red[t + s2];
        __syncthreads();
    }
    float mu = red[0] * (1.0f / 512.0f);
    __syncthreads();

    float d0 = v0 - mu, d1 = v1 - mu;
    red[t] = d0 * d0 + d1 * d1;
    __syncthreads();
    #pragma unroll
    for (int s2 = 128; s2 > 0; s2 >>= 1) {
        if (t < s2) red[t] += red[t + s2];
        __syncthreads();
    }
    float var = red[0] * (1.0f / 512.0f);
    float rs  = rsqrtf(var + 1e-3f);

    out[off + t]       = basep[off + t]       + scale * (d0 * rs * gamma[t]       + beta[t]);
    out[off + t + 256] = basep[off + t + 256] + scale * (d1 * rs * gamma[t + 256] + beta[t + 256]);
}

// ---------------- SGEMM: C[8192,512] = A[8192,512] @ W[512,512] (+ addend) ----------------
// f32x2 packed accumulators along M: acc[pu][v] holds rows (2pu, 2pu+1) of the 8-row strip.
#define GBM 128
#define GBN 64
#define GBK 16
__global__ void __launch_bounds__(256) sgemm_kernel(const float* __restrict__ A,
                                                    const float* __restrict__ W,
                                                    const float* __restrict__ addend,
                                                    float* __restrict__ C) {
    __shared__ __align__(16) float As[GBK][GBM + 4]; // transposed: As[k][m]
    __shared__ __align__(16) float Bs[GBK][GBN];

    int tid = threadIdx.x;
    int tx = tid & 15;       // n dir, 4 cols each
    int ty = tid >> 4;       // m dir, 4+4 rows each
    int m0 = blockIdx.y * GBM;
    int n0 = blockIdx.x * GBN;

    const float* Ap = A + (size_t)m0 * Dq;
    const float* Wp = W + n0;

    u64 acc[4][4];
    #pragma unroll
    for (int u = 0; u < 4; u++)
        #pragma unroll
        for (int v = 0; v < 4; v++) acc[u][v] = 0ull;  // two packed 0.0f

    for (int kt = 0; kt < Dq; kt += GBK) {
        // Load A tile 128x16 (transpose into As[k][m])
        #pragma unroll
        for (int p = 0; p < 8; p++) {
            int e = tid + p * 256;
            int r = e >> 4, c = e & 15;
            As[c][r] = Ap[r * Dq + kt + c];
        }
        // Load W tile 16x64
        #pragma unroll
        for (int p = 0; p < 4; p++) {
            int e = tid + p * 256;
            int r = e >> 6, c = e & 63;
            Bs[r][c] = Wp[(size_t)(kt + r) * Dq + c];
        }
        __syncthreads();

        #pragma unroll
        for (int k = 0; k < GBK; k++) {
            // A row pairs come packed for free from the transposed tile
            ulonglong2 a0 = *(const ulonglong2*)&As[k][ty * 4];        // rows (0,1),(2,3)
            ulonglong2 a1 = *(const ulonglong2*)&As[k][64 + ty * 4];   // rows (4,5),(6,7)
            float4 b = *(const float4*)&Bs[k][tx * 4];
            u64 ap[4] = {a0.x, a0.y, a1.x, a1.y};
            u64 bd[4] = {dup2(b.x), dup2(b.y), dup2(b.z), dup2(b.w)};
            #pragma unroll
            for (int u = 0; u < 4; u++)
                #pragma unroll
                for (int v = 0; v < 4; v++)
                    acc[u][v] = ffma2(ap[u], bd[v], acc[u][v]);
        }
        __syncthreads();
    }

    // Epilogue: each acc pair covers two consecutive rows
    #pragma unroll
    for (int pu = 0; pu < 4; pu++) {
        int rbase = m0 + ((pu >> 1) * 64) + ty * 4 + (pu & 1) * 2;
        float2 e0 = unpk(acc[pu][0]);
        float2 e1 = unpk(acc[pu][1]);
        float2 e2 = unpk(acc[pu][2]);
        float2 e3 = unpk(acc[pu][3]);
        size_t o0 = (size_t)rbase * Dq + n0 + tx * 4;
        size_t o1 = o0 + Dq;
        float4 rlo = make_float4(e0.x, e1.x, e2.x, e3.x);
        float4 rhi = make_float4(e0.y, e1.y, e2.y, e3.y);
        if (addend) {
            float4 a0v = *(const float4*)&addend[o0];
            float4 a1v = *(const float4*)&addend[o1];
            rlo.x += a0v.x; rlo.y += a0v.y; rlo.z += a0v.z; rlo.w += a0v.w;
            rhi.x += a1v.x; rhi.y += a1v.y; rhi.z += a1v.z; rhi.w += a1v.w;
        }
        *(float4*)&C[o0] = rlo;
        *(float4*)&C[o1] = rhi;
    }
}

// ---------------- Flash attention (scale = 1/H) ----------------
// 64 queries x one head per CTA. 256 threads = 16x16, 4x4 per thread.
// Distributed register softmax: 16-lane shfl reductions, per-thread (m,l,alpha).
#define FS_FLOATS (4096 + 4096 + 64*68)
#define FS_BYTES  (FS_FLOATS * 4)

__global__ void __launch_bounds__(256) flash_kernel(const float* __restrict__ Q,
                                                    const float* __restrict__ K,
                                                    const float* __restrict__ V,
                                                    float* __restrict__ O) {
    extern __shared__ float sm[];
    float* Qs  = sm;               // [r*64 + c]
    float* Vs  = sm + 4096;        // [r*64 + c]
    float* KtP = sm + 8192;        // Kt: [c*68 + r], later P: [i*68 + j]

    int tid = threadIdx.x;
    int tx = tid & 15, ty = tid >> 4;
    int i0 = ty * 4, j0 = tx * 4;
    int qb = blockIdx.x, h = blockIdx.y, b = blockIdx.z;

    const size_t baseQ  = ((size_t)b * Sq + (size_t)qb * 64) * Dq + h * DHq;
    const size_t baseKV = ((size_t)b * Sq) * Dq + h * DHq;

    // Load Q tile (64x64)
    #pragma unroll
    for (int p = 0; p < 16; p++) {
        int e = tid + p * 256;
        int r = e >> 6, c = e & 63;
        Qs[r * 64 + c] = Q[baseQ + (size_t)r * Dq + c];
    }

    u64 o2[4][2];      // output accumulators, packed along dh-pair
    #pragma unroll
    for (int u = 0; u < 4; u++) { o2[u][0] = 0ull; o2[u][1] = 0ull; }

    float m_r[4], l_r[4];
    #pragma unroll
    for (int u = 0; u < 4; u++) { m_r[u] = -1e30f; l_r[u] = 0.0f; }

    for (int kb = 0; kb < Sq / 64; kb++) {
        __syncthreads();  // protect KtP/Vs overwrite (and Qs on first iter)

        const float* Kp = K + baseKV + (size_t)kb * 64 * Dq;
        const float* Vp = V + baseKV + (size_t)kb * 64 * Dq;
        #pragma unroll
        for (int p = 0; p < 16; p++) {
            int e = tid + p * 256;
            int r = e >> 6, c = e & 63;
            KtP[c * 68 + r] = Kp[(size_t)r * Dq + c];  // transposed store
            Vs[r * 64 + c]  = Vp[(size_t)r * Dq + c];
        }
        __syncthreads();

        // S = Q @ K^T, packed along j-pairs
        u64 s2[4][2];
        #pragma unroll
        for (int u = 0; u < 4; u++) { s2[u][0] = 0ull; s2[u][1] = 0ull; }

        #pragma unroll
        for (int c = 0; c < 64; c += 4) {
            float4 q0 = *(const float4*)&Qs[(i0 + 0) * 64 + c];
            float4 q1 = *(const float4*)&Qs[(i0 + 1) * 64 + c];
            float4 q2 = *(const float4*)&Qs[(i0 + 2) * 64 + c];
            float4 q3 = *(const float4*)&Qs[(i0 + 3) * 64 + c];
            ulonglong2 k0 = *(const ulonglong2*)&KtP[(c + 0) * 68 + j0];
            ulonglong2 k1 = *(const ulonglong2*)&KtP[(c + 1) * 68 + j0];
            ulonglong2 k2 = *(const ulonglong2*)&KtP[(c + 2) * 68 + j0];
            ulonglong2 k3 = *(const ulonglong2*)&KtP[(c + 3) * 68 + j0];
            #define QKROW(u, qv) {                                            \
                u64 dx = dup2(qv.x), dy = dup2(qv.y);                         \
                u64 dz = dup2(qv.z), dw = dup2(qv.w);                         \
                s2[u][0] = ffma2(dx, k0.x, s2[u][0]);                         \
                s2[u][0] = ffma2(dy, k1.x, s2[u][0]);                         \
                s2[u][0] = ffma2(dz, k2.x, s2[u][0]);                         \
                s2[u][0] = ffma2(dw, k3.x, s2[u][0]);                         \
                s2[u][1] = ffma2(dx, k0.y, s2[u][1]);                         \
                s2[u][1] = ffma2(dy, k1.y, s2[u][1]);                         \
                s2[u][1] = ffma2(dz, k2.y, s2[u][1]);                         \
                s2[u][1] = ffma2(dw, k3.y, s2[u][1]);                         \
            }
            QKROW(0, q0) QKROW(1, q1) QKROW(2, q2) QKROW(3, q3)
            #undef QKROW
        }

        // Distributed softmax in registers (16-lane row groups; xor<=8 stays in group)
        float sc[4][4];
        float al[4];
        #pragma unroll
        for (int u = 0; u < 4; u++) {
            float2 e0 = unpk(s2[u][0]);
            float2 e1 = unpk(s2[u][1]);
            sc[u][0] = e0.x * 0.125f; sc[u][1] = e0.y * 0.125f;
            sc[u][2] = e1.x * 0.125f; sc[u][3] = e1.y * 0.125f;
            float mx = fmaxf(fmaxf(sc[u][0], sc[u][1]), fmaxf(sc[u][2], sc[u][3]));
            #pragma unroll
            for (int w = 1; w < 16; w <<= 1)
                mx = fmaxf(mx, __shfl_xor_sync(0xffffffffu, mx, w));
            float mnew = fmaxf(m_r[u], mx);
            al[u] = __expf(m_r[u] - mnew);
            float sum = 0.0f;
            #pragma unroll
            for (int v = 0; v < 4; v++) {
                float p = __expf(sc[u][v] - mnew);
                sc[u][v] = p;
                sum += p;
            }
            #pragma unroll
            for (int w = 1; w < 16; w <<= 1)
                sum += __shfl_xor_sync(0xffffffffu, sum, w);
            l_r[u] = l_r[u] * al[u] + sum;
            m_r[u] = mnew;
        }

        __syncthreads();  // all QK reads of KtP finished

        // Store P over the Kt region
        #pragma unroll
        for (int u = 0; u < 4; u++)
            *(float4*)&KtP[(i0 + u) * 68 + j0] =
                make_float4(sc[u][0], sc[u][1], sc[u][2], sc[u][3]);
        __syncthreads();

        // Rescale running O (per-thread alphas), then O += P @ V
        #pragma unroll
        for (int u = 0; u < 4; u++) {
            u64 ad = dup2(al[u]);
            o2[u][0] = fmul2(ad, o2[u][0]);
            o2[u][1] = fmul2(ad, o2[u][1]);
        }
        #pragma unroll
        for (int kk = 0; kk < 64; kk += 4) {
            float4 p0 = *(const float4*)&KtP[(i0 + 0) * 68 + kk];
            float4 p1 = *(const float4*)&KtP[(i0 + 1) * 68 + kk];
            float4 p2 = *(const float4*)&KtP[(i0 + 2) * 68 + kk];
            float4 p3 = *(const float4*)&KtP[(i0 + 3) * 68 + kk];
            ulonglong2 v0 = *(const ulonglong2*)&Vs[(kk + 0) * 64 + j0];
            ulonglong2 v1 = *(const ulonglong2*)&Vs[(kk + 1) * 64 + j0];
            ulonglong2 v2 = *(const ulonglong2*)&Vs[(kk + 2) * 64 + j0];
            ulonglong2 v3 = *(const ulonglong2*)&Vs[(kk + 3) * 64 + j0];
            #define PVROW(u, pv) {                                            \
                u64 dx = dup2(pv.x), dy = dup2(pv.y);                         \
                u64 dz = dup2(pv.z), dw = dup2(pv.w);                         \
                o2[u][0] = ffma2(dx, v0.x, o2[u][0]);                         \
                o2[u][0] = ffma2(dy, v1.x, o2[u][0]);                         \
                o2[u][0] = ffma2(dz, v2.x, o2[u][0]);                         \
                o2[u][0] = ffma2(dw, v3.x, o2[u][0]);                         \
                o2[u][1] = ffma2(dx, v0.y, o2[u][1]);                         \
                o2[u][1] = ffma2(dy, v1.y, o2[u][1]);                         \
                o2[u][1] = ffma2(dz, v2.y, o2[u][1]);                         \
                o2[u][1] = ffma2(dw, v3.y, o2[u][1]);                         \
            }
            PVROW(0, p0) PVROW(1, p1) PVROW(2, p2) PVROW(3, p3)
            #undef PVROW
        }
    }

    // Final normalize + store
    #pragma unroll
    for (int u = 0; u < 4; u++) {
        float li = 1.0f / l_r[u];
        float2 e0 = unpk(o2[u][0]);
        float2 e1 = unpk(o2[u][1]);
        *(float4*)&O[baseQ + (size_t)(i0 + u) * Dq + j0] =
            make_float4(e0.x * li, e0.y * li, e1.x * li, e1.y * li);
    }
}

// ---------------- launcher ----------------
extern "C" void kernel_launch(void* const* d_in, const int* in_sizes, int n_in,
                              void* d_out, int out_size) {
    const float* in0   = (const float*)d_in[0];
    const float* in1   = (const float*)d_in[1];
    const float* Wq_e  = (const float*)d_in[2];
    const float* Wk_e  = (const float*)d_in[3];
    const float* Wv_e  = (const float*)d_in[4];
    const float* Wff_e = (const float*)d_in[5];
    const float* ge    = (const float*)d_in[6];
    const float* be    = (const float*)d_in[7];
    const float* Wq_d  = (const float*)d_in[8];
    const float* Wk_d  = (const float*)d_in[9];
    const float* Wv_d  = (const float*)d_in[10];
    const float* Wff_d = (const float*)d_in[11];
    const float* gd    = (const float*)d_in[12];
    const float* bd    = (const float*)d_in[13];
    float* out = (float*)d_out;

    float *E, *DI, *Qb, *Kb, *Vb, *Sb, *I, *EO;
    cudaGetSymbolAddress((void**)&E,  g_E);
    cudaGetSymbolAddress((void**)&DI, g_DI);
    cudaGetSymbolAddress((void**)&Qb, g_Q);
    cudaGetSymbolAddress((void**)&Kb, g_K);
    cudaGetSymbolAddress((void**)&Vb, g_V);
    cudaGetSymbolAddress((void**)&Sb, g_S);
    cudaGetSymbolAddress((void**)&I,  g_I);
    cudaGetSymbolAddress((void**)&EO, g_EO);

    cudaFuncSetAttribute(flash_kernel, cudaFuncAttributeMaxDynamicSharedMemorySize, FS_BYTES);

    dim3 ggrid(Dq / GBN, BSr / GBM);      // (8, 64)
    dim3 fgrid(Sq / 64, Hq, Bq);          // (16, 8, 8)

    // ---- Encoder ----
    add_pos_kernel<<<BSD / 256, 256>>>(in0, E);
    sgemm_kernel<<<ggrid, 256>>>(E, Wq_e, nullptr, Qb);
    sgemm_kernel<<<ggrid, 256>>>(E, Wk_e, nullptr, Kb);
    sgemm_kernel<<<ggrid, 256>>>(E, Wv_e, nullptr, Vb);
    flash_kernel<<<fgrid, 256, FS_BYTES>>>(Qb, Kb, Vb, Sb);
    ln_add_kernel<<<BSr, 256>>>(Sb, ge, be, E, 1.0f, I);
    sgemm_kernel<<<ggrid, 256>>>(I, Wff_e, E, EO);

    // ---- Decoder ----
    add_pos_kernel<<<BSD / 256, 256>>>(in1, DI);
    sgemm_kernel<<<ggrid, 256>>>(DI, Wq_d, nullptr, Qb);
    sgemm_kernel<<<ggrid, 256>>>(DI, Wk_d, nullptr, Kb);
    sgemm_kernel<<<ggrid, 256>>>(DI, Wv_d, nullptr, Vb);
    flash_kernel<<<fgrid, 256, FS_BYTES>>>(Qb, Kb, Vb, Sb);
    ln_add_kernel<<<BSr, 256>>>(Sb, gd, bd, DI, 2.0f, I);
    flash_kernel<<<fgrid, 256, FS_BYTES>>>(EO, EO, EO, Qb);
    sgemm_kernel<<<ggrid, 256>>>(Qb, Wff_d, I, out);
}

// round 4
// speedup vs baseline: 1.7888x; 1.7888x over previous
#include <cuda_runtime.h>
#include <cuda_bf16.h>
#include <cstdint>
#include <math.h>

// Problem constants
#define Bq   8
#define Sq   1024
#define Dq   512
#define Hq   8
#define DHq  64
#define BSr  (Bq*Sq)        // 8192 rows
#define BSD  (Bq*Sq*Dq)     // 4194304 elements

// ---------------- device scratch (no allocations allowed) ----------------
__device__ float g_E [BSD];
__device__ float g_DI[BSD];
__device__ float g_Q [BSD];
__device__ float g_K [BSD];
__device__ float g_V [BSD];
__device__ float g_S [BSD];
__device__ float g_I [BSD];
__device__ float g_EO[BSD];
__device__ __nv_bfloat16 g_Ahi[BSD];
__device__ __nv_bfloat16 g_Alo[BSD];
__device__ __nv_bfloat16 g_Wthi[8 * Dq * Dq];   // transposed weights [n][k], hi part
__device__ __nv_bfloat16 g_Wtlo[8 * Dq * Dq];   // lo part

// ---------------- warp-mma helpers (non-'a' ISA only) ----------------
__device__ __forceinline__ uint32_t smem_u32(const void* p) {
    uint32_t a;
    asm("{ .reg .u64 t; cvta.to.shared.u64 t, %1; cvt.u32.u64 %0, t; }" : "=r"(a) : "l"(p));
    return a;
}
__device__ __forceinline__ void ldsm_x4(uint32_t* r, uint32_t addr) {
    asm volatile("ldmatrix.sync.aligned.m8n8.x4.shared.b16 {%0,%1,%2,%3}, [%4];"
        : "=r"(r[0]), "=r"(r[1]), "=r"(r[2]), "=r"(r[3]) : "r"(addr));
}
__device__ __forceinline__ void ldsm_x2(uint32_t* r, uint32_t addr) {
    asm volatile("ldmatrix.sync.aligned.m8n8.x2.shared.b16 {%0,%1}, [%2];"
        : "=r"(r[0]), "=r"(r[1]) : "r"(addr));
}
__device__ __forceinline__ void mma16816(float* c, const uint32_t* a, const uint32_t* b) {
    asm volatile("mma.sync.aligned.m16n8k16.row.col.f32.bf16.bf16.f32 "
        "{%0,%1,%2,%3}, {%4,%5,%6,%7}, {%8,%9}, {%0,%1,%2,%3};"
        : "+f"(c[0]), "+f"(c[1]), "+f"(c[2]), "+f"(c[3])
        : "r"(a[0]), "r"(a[1]), "r"(a[2]), "r"(a[3]), "r"(b[0]), "r"(b[1]));
}

// ---------------- conversion kernels ----------------
__global__ void __launch_bounds__(256) cvt_act_kernel(const float* __restrict__ x,
                                                      __nv_bfloat16* __restrict__ hi,
                                                      __nv_bfloat16* __restrict__ lo) {
    int i = (blockIdx.x * 256 + threadIdx.x) * 4;
    float4 v = *(const float4*)&x[i];
    __nv_bfloat16 h0 = __float2bfloat16(v.x), h1 = __float2bfloat16(v.y);
    __nv_bfloat16 h2 = __float2bfloat16(v.z), h3 = __float2bfloat16(v.w);
    __nv_bfloat162 H0, H1;
    H0.x = h0; H0.y = h1; H1.x = h2; H1.y = h3;
    *(__nv_bfloat162*)&hi[i]     = H0;
    *(__nv_bfloat162*)&hi[i + 2] = H1;
    __nv_bfloat162 L0, L1;
    L0.x = __float2bfloat16(v.x - __bfloat162float(h0));
    L0.y = __float2bfloat16(v.y - __bfloat162float(h1));
    L1.x = __float2bfloat16(v.z - __bfloat162float(h2));
    L1.y = __float2bfloat16(v.w - __bfloat162float(h3));
    *(__nv_bfloat162*)&lo[i]     = L0;
    *(__nv_bfloat162*)&lo[i + 2] = L1;
}

// Weight convert + transpose: out[n*512+k] = split(W[k*512+n])
__global__ void __launch_bounds__(256) cvt_wt_kernel(const float* __restrict__ W,
                                                     __nv_bfloat16* __restrict__ hi,
                                                     __nv_bfloat16* __restrict__ lo) {
    int idx = blockIdx.x * 256 + threadIdx.x;   // idx = n*512 + k
    int n = idx >> 9, k = idx & 511;
    float v = W[k * Dq + n];
    __nv_bfloat16 h = __float2bfloat16(v);
    hi[idx] = h;
    lo[idx] = __float2bfloat16(v - __bfloat162float(h));
}

// ---------------- mma.sync split-bf16 GEMM ----------------
// C[8192,512] = A @ W (+addend). CTA tile 128x64, K-chunk 64.
// 8 warps: warp_m = wid&3 (32 rows), warp_n = wid>>2 (32 cols).
// smem rows padded to 72 elements (144B) -> conflict-free ldmatrix groups.
#define APAD 72
#define SA_HI 0
#define SA_LO 18432
#define SB_HI 36864
#define SB_LO 46080
#define GEMM_SMEM 55296

__global__ void __launch_bounds__(256) gemm_mma_kernel(const __nv_bfloat16* __restrict__ Ahi,
                                                       const __nv_bfloat16* __restrict__ Alo,
                                                       const __nv_bfloat16* __restrict__ Bhi,
                                                       const __nv_bfloat16* __restrict__ Blo,
                                                       const float* __restrict__ addend,
                                                       float* __restrict__ C) {
    extern __shared__ char smem[];
    uint32_t sb = smem_u32(smem);
    __nv_bfloat16* sAhi = (__nv_bfloat16*)(smem + SA_HI);
    __nv_bfloat16* sAlo = (__nv_bfloat16*)(smem + SA_LO);
    __nv_bfloat16* sBhi = (__nv_bfloat16*)(smem + SB_HI);
    __nv_bfloat16* sBlo = (__nv_bfloat16*)(smem + SB_LO);

    int tid = threadIdx.x;
    int wid = tid >> 5, lane = tid & 31;
    int wm = (wid & 3) * 32;      // warp row offset in CTA tile
    int wn = (wid >> 2) * 32;     // warp col offset
    int m0 = blockIdx.y * 128;
    int n0 = blockIdx.x * 64;

    float acc[2][4][4];
    #pragma unroll
    for (int i = 0; i < 2; i++)
        #pragma unroll
        for (int j = 0; j < 4; j++)
            #pragma unroll
            for (int q = 0; q < 4; q++) acc[i][j][q] = 0.0f;

    // Precomputed ldmatrix lane addresses (element offsets within tile)
    int la = lane & 15;            // A: row within 16-row atom
    int lacol = (lane >> 4) << 3;  // A: 0 or 8 col offset
    int lb = lane & 7;             // B: row within 8-row atom (n dir)
    int lbcol = ((lane >> 3) & 1) << 3;  // B: 0 or 8 (k offset), lanes 0-15 used

    for (int kc = 0; kc < 8; kc++) {
        int kofs = kc * 64;
        // Load A tiles 128x64 (hi & lo)
        #pragma unroll
        for (int p = 0; p < 4; p++) {
            int e = tid + p * 256;
            int r = e >> 3, c8 = (e & 7) * 8;
            size_t go = (size_t)(m0 + r) * Dq + kofs + c8;
            *(uint4*)&sAhi[r * APAD + c8] = *(const uint4*)&Ahi[go];
            *(uint4*)&sAlo[r * APAD + c8] = *(const uint4*)&Alo[go];
        }
        // Load B tiles 64x64 (hi & lo), B stored [n][k]
        #pragma unroll
        for (int p = 0; p < 2; p++) {
            int e = tid + p * 256;
            int r = e >> 3, c8 = (e & 7) * 8;
            size_t go = (size_t)(n0 + r) * Dq + kofs + c8;
            *(uint4*)&sBhi[r * APAD + c8] = *(const uint4*)&Bhi[go];
            *(uint4*)&sBlo[r * APAD + c8] = *(const uint4*)&Blo[go];
        }
        __syncthreads();

        #pragma unroll
        for (int ks = 0; ks < 4; ks++) {
            int kk = ks * 16;
            uint32_t ah[2][4], al[2][4];
            #pragma unroll
            for (int ma = 0; ma < 2; ma++) {
                int row = wm + ma * 16 + la;
                uint32_t off = (uint32_t)((row * APAD + kk + lacol) * 2);
                ldsm_x4(ah[ma], sb + SA_HI + off);
                ldsm_x4(al[ma], sb + SA_LO + off);
            }
            uint32_t bh[4][2], bl[4][2];
            #pragma unroll
            for (int na = 0; na < 4; na++) {
                int rown = wn + na * 8 + lb;
                uint32_t off = (uint32_t)((rown * APAD + kk + lbcol) * 2);
                ldsm_x2(bh[na], sb + SB_HI + off);
                ldsm_x2(bl[na], sb + SB_LO + off);
            }
            #pragma unroll
            for (int ma = 0; ma < 2; ma++)
                #pragma unroll
                for (int na = 0; na < 4; na++) {
                    mma16816(acc[ma][na], ah[ma], bh[na]);
                    mma16816(acc[ma][na], al[ma], bh[na]);
                    mma16816(acc[ma][na], ah[ma], bl[na]);
                }
        }
        __syncthreads();
    }

    // Epilogue: c0,c1 -> (row, col..col+1); c2,c3 -> (row+8, ...)
    int g = lane >> 2, tq = lane & 3;
    #pragma unroll
    for (int ma = 0; ma < 2; ma++) {
        int row = m0 + wm + ma * 16 + g;
        #pragma unroll
        for (int na = 0; na < 4; na++) {
            int col = n0 + wn + na * 8 + tq * 2;
            size_t o0 = (size_t)row * Dq + col;
            size_t o1 = o0 + 8 * Dq;
            float2 r0 = make_float2(acc[ma][na][0], acc[ma][na][1]);
            float2 r1 = make_float2(acc[ma][na][2], acc[ma][na][3]);
            if (addend) {
                float2 a0 = *(const float2*)&addend[o0];
                float2 a1 = *(const float2*)&addend[o1];
                r0.x += a0.x; r0.y += a0.y;
                r1.x += a1.x; r1.y += a1.y;
            }
            *(float2*)&C[o0] = r0;
            *(float2*)&C[o1] = r1;
        }
    }
}

// ---------------- positional-embedding add ----------------
__global__ void __launch_bounds__(256) add_pos_kernel(const float* __restrict__ x,
                                                      float* __restrict__ out) {
    int idx = blockIdx.x * 256 + threadIdx.x;
    int d = idx & (Dq - 1);
    int s = (idx >> 9) & (Sq - 1);
    float freq  = expf((float)d * -0.0359778920794f);
    float angle = (float)s * freq;
    float pe = (d & 1) ? cosf(angle) : sinf(angle);
    out[idx] = x[idx] + pe;
}

// ---------------- fused LayerNorm + residual ----------------
__global__ void __launch_bounds__(256) ln_add_kernel(const float* __restrict__ x,
                                                     const float* __restrict__ gamma,
                                                     const float* __restrict__ beta,
                                                     const float* __restrict__ basep,
                                                     float scale,
                                                     float* __restrict__ out) {
    __shared__ float red[256];
    int t = threadIdx.x;
    size_t off = (size_t)blockIdx.x * Dq;

    float v0 = x[off + t];
    float v1 = x[off + t + 256];

    red[t] = v0 + v1;
    __syncthreads();
    #pragma unroll
    for (int s2 = 128; s2 > 0; s2 >>= 1) {
        if (t < s2) red[t] += red[t + s2];
        __syncthreads();
    }
    float mu = red[0] * (1.0f / 512.0f);
    __syncthreads();

    float d0 = v0 - mu, d1 = v1 - mu;
    red[t] = d0 * d0 + d1 * d1;
    __syncthreads();
    #pragma unroll
    for (int s2 = 128; s2 > 0; s2 >>= 1) {
        if (t < s2) red[t] += red[t + s2];
        __syncthreads();
    }
    float var = red[0] * (1.0f / 512.0f);
    float rs  = rsqrtf(var + 1e-3f);

    out[off + t]       = basep[off + t]       + scale * (d0 * rs * gamma[t]       + beta[t]);
    out[off + t + 256] = basep[off + t + 256] + scale * (d1 * rs * gamma[t + 256] + beta[t + 256]);
}

// ---------------- Flash attention (scalar, R1 version; scale = 1/H) ----------------
#define FS_FLOATS (4096 + 4096 + 64*68 + 64)
#define FS_BYTES  (FS_FLOATS * 4)

__global__ void __launch_bounds__(256) flash_kernel(const float* __restrict__ Q,
                                                    const float* __restrict__ K,
                                                    const float* __restrict__ V,
                                                    float* __restrict__ O) {
    extern __shared__ float sm[];
    float* Qs     = sm;
    float* Vs     = sm + 4096;
    float* KtP    = sm + 8192;
    float* alphas = sm + 8192 + 64 * 68;

    int tid = threadIdx.x;
    int tx = tid & 15, ty = tid >> 4;
    int i0 = ty * 4, j0 = tx * 4;
    int qb = blockIdx.x, h = blockIdx.y, b = blockIdx.z;

    const size_t baseQ  = ((size_t)b * Sq + (size_t)qb * 64) * Dq + h * DHq;
    const size_t baseKV = ((size_t)b * Sq) * Dq + h * DHq;

    #pragma unroll
    for (int p = 0; p < 16; p++) {
        int e = tid + p * 256;
        int r = e >> 6, c = e & 63;
        Qs[r * 64 + c] = Q[baseQ + (size_t)r * Dq + c];
    }

    float o[4][4];
    #pragma unroll
    for (int u = 0; u < 4; u++)
        #pragma unroll
        for (int v = 0; v < 4; v++) o[u][v] = 0.0f;

    float m_t = -1e30f, l_t = 0.0f;

    for (int kb = 0; kb < Sq / 64; kb++) {
        __syncthreads();

        const float* Kp = K + baseKV + (size_t)kb * 64 * Dq;
        const float* Vp = V + baseKV + (size_t)kb * 64 * Dq;
        #pragma unroll
        for (int p = 0; p < 16; p++) {
            int e = tid + p * 256;
            int r = e >> 6, c = e & 63;
            KtP[c * 68 + r] = Kp[(size_t)r * Dq + c];
            Vs[r * 64 + c]  = Vp[(size_t)r * Dq + c];
        }
        __syncthreads();

        float s[4][4];
        #pragma unroll
        for (int u = 0; u < 4; u++)
            #pragma unroll
            for (int v = 0; v < 4; v++) s[u][v] = 0.0f;

        #pragma unroll
        for (int c = 0; c < 64; c += 4) {
            float4 q0 = *(const float4*)&Qs[(i0 + 0) * 64 + c];
            float4 q1 = *(const float4*)&Qs[(i0 + 1) * 64 + c];
            float4 q2 = *(const float4*)&Qs[(i0 + 2) * 64 + c];
            float4 q3 = *(const float4*)&Qs[(i0 + 3) * 64 + c];
            float4 k0 = *(const float4*)&KtP[(c + 0) * 68 + j0];
            float4 k1 = *(const float4*)&KtP[(c + 1) * 68 + j0];
            float4 k2 = *(const float4*)&KtP[(c + 2) * 68 + j0];
            float4 k3 = *(const float4*)&KtP[(c + 3) * 68 + j0];
            #define QKROW(u, qv)                                              \
                s[u][0] += qv.x*k0.x + qv.y*k1.x + qv.z*k2.x + qv.w*k3.x;     \
                s[u][1] += qv.x*k0.y + qv.y*k1.y + qv.z*k2.y + qv.w*k3.y;     \
                s[u][2] += qv.x*k0.z + qv.y*k1.z + qv.z*k2.z + qv.w*k3.z;     \
                s[u][3] += qv.x*k0.w + qv.y*k1.w + qv.z*k2.w + qv.w*k3.w;
            QKROW(0, q0) QKROW(1, q1) QKROW(2, q2) QKROW(3, q3)
            #undef QKROW
        }
        __syncthreads();

        #pragma unroll
        for (int u = 0; u < 4; u++) {
            float4 pv;
            pv.x = s[u][0] * 0.125f; pv.y = s[u][1] * 0.125f;
            pv.z = s[u][2] * 0.125f; pv.w = s[u][3] * 0.125f;
            *(float4*)&KtP[(i0 + u) * 68 + j0] = pv;
        }
        __syncthreads();

        if (tid < 64) {
            float* row = &KtP[tid * 68];
            float mx = row[0];
            #pragma unroll 8
            for (int j = 1; j < 64; j++) mx = fmaxf(mx, row[j]);
            float mnew  = fmaxf(m_t, mx);
            float alpha = __expf(m_t - mnew);
            float sum = 0.0f;
            #pragma unroll 8
            for (int j = 0; j < 64; j++) {
                float p = __expf(row[j] - mnew);
                row[j] = p;
                sum += p;
            }
            l_t = l_t * alpha + sum;
            m_t = mnew;
            alphas[tid] = alpha;
        }
        __syncthreads();

        float a0 = alphas[i0 + 0], a1 = alphas[i0 + 1];
        float a2 = alphas[i0 + 2], a3 = alphas[i0 + 3];
        #pragma unroll
        for (int v = 0; v < 4; v++) {
            o[0][v] *= a0; o[1][v] *= a1; o[2][v] *= a2; o[3][v] *= a3;
        }
        #pragma unroll
        for (int kk = 0; kk < 64; kk += 4) {
            float4 p0 = *(const float4*)&KtP[(i0 + 0) * 68 + kk];
            float4 p1 = *(const float4*)&KtP[(i0 + 1) * 68 + kk];
            float4 p2 = *(const float4*)&KtP[(i0 + 2) * 68 + kk];
            float4 p3 = *(const float4*)&KtP[(i0 + 3) * 68 + kk];
            float4 v0 = *(const float4*)&Vs[(kk + 0) * 64 + j0];
            float4 v1 = *(const float4*)&Vs[(kk + 1) * 64 + j0];
            float4 v2 = *(const float4*)&Vs[(kk + 2) * 64 + j0];
            float4 v3 = *(const float4*)&Vs[(kk + 3) * 64 + j0];
            #define PVROW(u, pv)                                              \
                o[u][0] += pv.x*v0.x + pv.y*v1.x + pv.z*v2.x + pv.w*v3.x;     \
                o[u][1] += pv.x*v0.y + pv.y*v1.y + pv.z*v2.y + pv.w*v3.y;     \
                o[u][2] += pv.x*v0.z + pv.y*v1.z + pv.z*v2.z + pv.w*v3.z;     \
                o[u][3] += pv.x*v0.w + pv.y*v1.w + pv.z*v2.w + pv.w*v3.w;
            PVROW(0, p0) PVROW(1, p1) PVROW(2, p2) PVROW(3, p3)
            #undef PVROW
        }
    }

    __syncthreads();
    if (tid < 64) alphas[tid] = 1.0f / l_t;
    __syncthreads();

    #pragma unroll
    for (int u = 0; u < 4; u++) {
        float li = alphas[i0 + u];
        float4 r;
        r.x = o[u][0] * li; r.y = o[u][1] * li;
        r.z = o[u][2] * li; r.w = o[u][3] * li;
        *(float4*)&O[baseQ + (size_t)(i0 + u) * Dq + j0] = r;
    }
}

// ---------------- launcher ----------------
extern "C" void kernel_launch(void* const* d_in, const int* in_sizes, int n_in,
                              void* d_out, int out_size) {
    const float* in0   = (const float*)d_in[0];
    const float* in1   = (const float*)d_in[1];
    const float* Wraw[8] = {
        (const float*)d_in[2],  (const float*)d_in[3],  (const float*)d_in[4],
        (const float*)d_in[5],  (const float*)d_in[8],  (const float*)d_in[9],
        (const float*)d_in[10], (const float*)d_in[11]
    };
    const float* ge = (const float*)d_in[6];
    const float* be = (const float*)d_in[7];
    const float* gd = (const float*)d_in[12];
    const float* bd = (const float*)d_in[13];
    float* out = (float*)d_out;

    float *E, *DI, *Qb, *Kb, *Vb, *Sb, *I, *EO;
    __nv_bfloat16 *Ahi, *Alo, *Whi, *Wlo;
    cudaGetSymbolAddress((void**)&E,   g_E);
    cudaGetSymbolAddress((void**)&DI,  g_DI);
    cudaGetSymbolAddress((void**)&Qb,  g_Q);
    cudaGetSymbolAddress((void**)&Kb,  g_K);
    cudaGetSymbolAddress((void**)&Vb,  g_V);
    cudaGetSymbolAddress((void**)&Sb,  g_S);
    cudaGetSymbolAddress((void**)&I,   g_I);
    cudaGetSymbolAddress((void**)&EO,  g_EO);
    cudaGetSymbolAddress((void**)&Ahi, g_Ahi);
    cudaGetSymbolAddress((void**)&Alo, g_Alo);
    cudaGetSymbolAddress((void**)&Whi, g_Wthi);
    cudaGetSymbolAddress((void**)&Wlo, g_Wtlo);

    cudaFuncSetAttribute(flash_kernel,    cudaFuncAttributeMaxDynamicSharedMemorySize, FS_BYTES);
    cudaFuncSetAttribute(gemm_mma_kernel, cudaFuncAttributeMaxDynamicSharedMemorySize, GEMM_SMEM);

    dim3 ggrid(Dq / 64, BSr / 128);       // (8, 64)
    dim3 fgrid(Sq / 64, Hq, Bq);          // (16, 8, 8)
    const int WSZ = Dq * Dq;              // 262144 per weight

    // Weight conversions (transposed, split bf16)
    for (int w = 0; w < 8; w++)
        cvt_wt_kernel<<<WSZ / 256, 256>>>(Wraw[w], Whi + w * WSZ, Wlo + w * WSZ);

    // ---- Encoder ----
    add_pos_kernel<<<BSD / 256, 256>>>(in0, E);
    cvt_act_kernel<<<BSD / 1024, 256>>>(E, Ahi, Alo);
    gemm_mma_kernel<<<ggrid, 256, GEMM_SMEM>>>(Ahi, Alo, Whi + 0 * WSZ, Wlo + 0 * WSZ, nullptr, Qb);
    gemm_mma_kernel<<<ggrid, 256, GEMM_SMEM>>>(Ahi, Alo, Whi + 1 * WSZ, Wlo + 1 * WSZ, nullptr, Kb);
    gemm_mma_kernel<<<ggrid, 256, GEMM_SMEM>>>(Ahi, Alo, Whi + 2 * WSZ, Wlo + 2 * WSZ, nullptr, Vb);
    flash_kernel<<<fgrid, 256, FS_BYTES>>>(Qb, Kb, Vb, Sb);
    ln_add_kernel<<<BSr, 256>>>(Sb, ge, be, E, 1.0f, I);
    cvt_act_kernel<<<BSD / 1024, 256>>>(I, Ahi, Alo);
    gemm_mma_kernel<<<ggrid, 256, GEMM_SMEM>>>(Ahi, Alo, Whi + 3 * WSZ, Wlo + 3 * WSZ, E, EO);

    // ---- Decoder ----
    add_pos_kernel<<<BSD / 256, 256>>>(in1, DI);
    cvt_act_kernel<<<BSD / 1024, 256>>>(DI, Ahi, Alo);
    gemm_mma_kernel<<<ggrid, 256, GEMM_SMEM>>>(Ahi, Alo, Whi + 4 * WSZ, Wlo + 4 * WSZ, nullptr, Qb);
    gemm_mma_kernel<<<ggrid, 256, GEMM_SMEM>>>(Ahi, Alo, Whi + 5 * WSZ, Wlo + 5 * WSZ, nullptr, Kb);
    gemm_mma_kernel<<<ggrid, 256, GEMM_SMEM>>>(Ahi, Alo, Whi + 6 * WSZ, Wlo + 6 * WSZ, nullptr, Vb);
    flash_kernel<<<fgrid, 256, FS_BYTES>>>(Qb, Kb, Vb, Sb);
    ln_add_kernel<<<BSr, 256>>>(Sb, gd, bd, DI, 2.0f, I);
    flash_kernel<<<fgrid, 256, FS_BYTES>>>(EO, EO, EO, Qb);       // eda
    cvt_act_kernel<<<BSD / 1024, 256>>>(Qb, Ahi, Alo);
    gemm_mma_kernel<<<ggrid, 256, GEMM_SMEM>>>(Ahi, Alo, Whi + 7 * WSZ, Wlo + 7 * WSZ, I, out);
}

// round 5
// speedup vs baseline: 3.7496x; 2.0961x over previous
#include <cuda_runtime.h>
#include <cuda_bf16.h>
#include <cstdint>
#include <math.h>

// Problem constants
#define Bq   8
#define Sq   1024
#define Dq   512
#define Hq   8
#define DHq  64
#define BSr  (Bq*Sq)        // 8192 rows
#define BSD  (Bq*Sq*Dq)     // 4194304 elements

// ---------------- device scratch (no allocations allowed) ----------------
__device__ float g_E [BSD];
__device__ float g_DI[BSD];
__device__ float g_S [BSD];
__device__ float g_I [BSD];
__device__ float g_EO[BSD];
__device__ __nv_bfloat16 g_Ahi[BSD], g_Alo[BSD];
__device__ __nv_bfloat16 g_Qhi[BSD], g_Qlo[BSD];
__device__ __nv_bfloat16 g_Khi[BSD], g_Klo[BSD];
__device__ __nv_bfloat16 g_Vhi[BSD], g_Vlo[BSD];
__device__ __nv_bfloat16 g_EOhi[BSD], g_EOlo[BSD];
__device__ __nv_bfloat16 g_Wthi[8 * Dq * Dq];   // transposed weights [n][k], hi
__device__ __nv_bfloat16 g_Wtlo[8 * Dq * Dq];   // lo

// ---------------- warp-mma helpers (non-'a' ISA only) ----------------
__device__ __forceinline__ uint32_t smem_u32(const void* p) {
    uint32_t a;
    asm("{ .reg .u64 t; cvta.to.shared.u64 t, %1; cvt.u32.u64 %0, t; }" : "=r"(a) : "l"(p));
    return a;
}
__device__ __forceinline__ void ldsm_x4(uint32_t* r, uint32_t addr) {
    asm volatile("ldmatrix.sync.aligned.m8n8.x4.shared.b16 {%0,%1,%2,%3}, [%4];"
        : "=r"(r[0]), "=r"(r[1]), "=r"(r[2]), "=r"(r[3]) : "r"(addr));
}
__device__ __forceinline__ void ldsm_x2(uint32_t* r, uint32_t addr) {
    asm volatile("ldmatrix.sync.aligned.m8n8.x2.shared.b16 {%0,%1}, [%2];"
        : "=r"(r[0]), "=r"(r[1]) : "r"(addr));
}
__device__ __forceinline__ void ldsm_x2t(uint32_t* r, uint32_t addr) {
    asm volatile("ldmatrix.sync.aligned.m8n8.x2.trans.shared.b16 {%0,%1}, [%2];"
        : "=r"(r[0]), "=r"(r[1]) : "r"(addr));
}
__device__ __forceinline__ void mma16816(float* c, const uint32_t* a, const uint32_t* b) {
    asm volatile("mma.sync.aligned.m16n8k16.row.col.f32.bf16.bf16.f32 "
        "{%0,%1,%2,%3}, {%4,%5,%6,%7}, {%8,%9}, {%0,%1,%2,%3};"
        : "+f"(c[0]), "+f"(c[1]), "+f"(c[2]), "+f"(c[3])
        : "r"(a[0]), "r"(a[1]), "r"(a[2]), "r"(a[3]), "r"(b[0]), "r"(b[1]));
}
// split a pair of fp32 into hi/lo bf16x2 (packed u32, low half = first elem)
__device__ __forceinline__ void splitpk(float a, float b, uint32_t& hi, uint32_t& lo) {
    __nv_bfloat162 h = __floats2bfloat162_rn(a, b);
    float ra = a - __bfloat162float(h.x);
    float rb = b - __bfloat162float(h.y);
    __nv_bfloat162 l = __floats2bfloat162_rn(ra, rb);
    hi = *(uint32_t*)&h; lo = *(uint32_t*)&l;
}

// ---------------- weight convert + transpose ----------------
__global__ void __launch_bounds__(256) cvt_wt_kernel(const float* __restrict__ W,
                                                     __nv_bfloat16* __restrict__ hi,
                                                     __nv_bfloat16* __restrict__ lo) {
    int idx = blockIdx.x * 256 + threadIdx.x;   // idx = n*512 + k
    int n = idx >> 9, k = idx & 511;
    float v = W[k * Dq + n];
    __nv_bfloat16 h = __float2bfloat16(v);
    hi[idx] = h;
    lo[idx] = __float2bfloat16(v - __bfloat162float(h));
}

// ---------------- positional-embedding add (fp32 + split bf16 out) ----------------
__global__ void __launch_bounds__(256) add_pos_kernel(const float* __restrict__ x,
                                                      float* __restrict__ out,
                                                      __nv_bfloat16* __restrict__ ohi,
                                                      __nv_bfloat16* __restrict__ olo) {
    int idx = blockIdx.x * 256 + threadIdx.x;
    int d = idx & (Dq - 1);
    int s = (idx >> 9) & (Sq - 1);
    float freq  = expf((float)d * -0.0359778920794f);
    float angle = (float)s * freq;
    float pe = (d & 1) ? cosf(angle) : sinf(angle);
    float r = x[idx] + pe;
    out[idx] = r;
    __nv_bfloat16 h = __float2bfloat16(r);
    ohi[idx] = h;
    olo[idx] = __float2bfloat16(r - __bfloat162float(h));
}

// ---------------- fused LayerNorm + residual (fp32 + split bf16 out) ----------------
__global__ void __launch_bounds__(256) ln_add_kernel(const float* __restrict__ x,
                                                     const float* __restrict__ gamma,
                                                     const float* __restrict__ beta,
                                                     const float* __restrict__ basep,
                                                     float scale,
                                                     float* __restrict__ out,
                                                     __nv_bfloat16* __restrict__ ohi,
                                                     __nv_bfloat16* __restrict__ olo) {
    __shared__ float red[256];
    int t = threadIdx.x;
    size_t off = (size_t)blockIdx.x * Dq;

    float v0 = x[off + t];
    float v1 = x[off + t + 256];

    red[t] = v0 + v1;
    __syncthreads();
    #pragma unroll
    for (int s2 = 128; s2 > 0; s2 >>= 1) {
        if (t < s2) red[t] += red[t + s2];
        __syncthreads();
    }
    float mu = red[0] * (1.0f / 512.0f);
    __syncthreads();

    float d0 = v0 - mu, d1 = v1 - mu;
    red[t] = d0 * d0 + d1 * d1;
    __syncthreads();
    #pragma unroll
    for (int s2 = 128; s2 > 0; s2 >>= 1) {
        if (t < s2) red[t] += red[t + s2];
        __syncthreads();
    }
    float var = red[0] * (1.0f / 512.0f);
    float rs  = rsqrtf(var + 1e-3f);

    float r0 = basep[off + t]       + scale * (d0 * rs * gamma[t]       + beta[t]);
    float r1 = basep[off + t + 256] + scale * (d1 * rs * gamma[t + 256] + beta[t + 256]);
    out[off + t]       = r0;
    out[off + t + 256] = r1;
    __nv_bfloat16 h0 = __float2bfloat16(r0), h1 = __float2bfloat16(r1);
    ohi[off + t]       = h0;
    ohi[off + t + 256] = h1;
    olo[off + t]       = __float2bfloat16(r0 - __bfloat162float(h0));
    olo[off + t + 256] = __float2bfloat16(r1 - __bfloat162float(h1));
}

// ---------------- mma.sync split-bf16 GEMM ----------------
#define APAD 72
#define SA_HI 0
#define SA_LO 18432
#define SB_HI 36864
#define SB_LO 46080
#define GEMM_SMEM 55296

__global__ void __launch_bounds__(256) gemm_mma_kernel(const __nv_bfloat16* __restrict__ Ahi,
                                                       const __nv_bfloat16* __restrict__ Alo,
                                                       const __nv_bfloat16* __restrict__ Bhi,
                                                       const __nv_bfloat16* __restrict__ Blo,
                                                       const float* __restrict__ addend,
                                                       float* __restrict__ C,
                                                       __nv_bfloat16* __restrict__ Chi,
                                                       __nv_bfloat16* __restrict__ Clo) {
    extern __shared__ char smem[];
    uint32_t sb = smem_u32(smem);
    __nv_bfloat16* sAhi = (__nv_bfloat16*)(smem + SA_HI);
    __nv_bfloat16* sAlo = (__nv_bfloat16*)(smem + SA_LO);
    __nv_bfloat16* sBhi = (__nv_bfloat16*)(smem + SB_HI);
    __nv_bfloat16* sBlo = (__nv_bfloat16*)(smem + SB_LO);

    int tid = threadIdx.x;
    int wid = tid >> 5, lane = tid & 31;
    int wm = (wid & 3) * 32;
    int wn = (wid >> 2) * 32;
    int m0 = blockIdx.y * 128;
    int n0 = blockIdx.x * 64;

    float acc[2][4][4];
    #pragma unroll
    for (int i = 0; i < 2; i++)
        #pragma unroll
        for (int j = 0; j < 4; j++)
            #pragma unroll
            for (int q = 0; q < 4; q++) acc[i][j][q] = 0.0f;

    int la = lane & 15;
    int lacol = (lane >> 4) << 3;
    int lb = lane & 7;
    int lbcol = ((lane >> 3) & 1) << 3;

    for (int kc = 0; kc < 8; kc++) {
        int kofs = kc * 64;
        #pragma unroll
        for (int p = 0; p < 4; p++) {
            int e = tid + p * 256;
            int r = e >> 3, c8 = (e & 7) * 8;
            size_t go = (size_t)(m0 + r) * Dq + kofs + c8;
            *(uint4*)&sAhi[r * APAD + c8] = *(const uint4*)&Ahi[go];
            *(uint4*)&sAlo[r * APAD + c8] = *(const uint4*)&Alo[go];
        }
        #pragma unroll
        for (int p = 0; p < 2; p++) {
            int e = tid + p * 256;
            int r = e >> 3, c8 = (e & 7) * 8;
            size_t go = (size_t)(n0 + r) * Dq + kofs + c8;
            *(uint4*)&sBhi[r * APAD + c8] = *(const uint4*)&Bhi[go];
            *(uint4*)&sBlo[r * APAD + c8] = *(const uint4*)&Blo[go];
        }
        __syncthreads();

        #pragma unroll
        for (int ks = 0; ks < 4; ks++) {
            int kk = ks * 16;
            uint32_t ah[2][4], al[2][4];
            #pragma unroll
            for (int ma = 0; ma < 2; ma++) {
                int row = wm + ma * 16 + la;
                uint32_t off = (uint32_t)((row * APAD + kk + lacol) * 2);
                ldsm_x4(ah[ma], sb + SA_HI + off);
                ldsm_x4(al[ma], sb + SA_LO + off);
            }
            uint32_t bh[4][2], bl[4][2];
            #pragma unroll
            for (int na = 0; na < 4; na++) {
                int rown = wn + na * 8 + lb;
                uint32_t off = (uint32_t)((rown * APAD + kk + lbcol) * 2);
                ldsm_x2(bh[na], sb + SB_HI + off);
                ldsm_x2(bl[na], sb + SB_LO + off);
            }
            #pragma unroll
            for (int ma = 0; ma < 2; ma++)
                #pragma unroll
                for (int na = 0; na < 4; na++) {
                    mma16816(acc[ma][na], ah[ma], bh[na]);
                    mma16816(acc[ma][na], al[ma], bh[na]);
                    mma16816(acc[ma][na], ah[ma], bl[na]);
                }
        }
        __syncthreads();
    }

    int g = lane >> 2, tq = lane & 3;
    #pragma unroll
    for (int ma = 0; ma < 2; ma++) {
        int row = m0 + wm + ma * 16 + g;
        #pragma unroll
        for (int na = 0; na < 4; na++) {
            int col = n0 + wn + na * 8 + tq * 2;
            size_t o0 = (size_t)row * Dq + col;
            size_t o1 = o0 + 8 * Dq;
            float2 r0 = make_float2(acc[ma][na][0], acc[ma][na][1]);
            float2 r1 = make_float2(acc[ma][na][2], acc[ma][na][3]);
            if (addend) {
                float2 a0 = *(const float2*)&addend[o0];
                float2 a1 = *(const float2*)&addend[o1];
                r0.x += a0.x; r0.y += a0.y;
                r1.x += a1.x; r1.y += a1.y;
            }
            if (C) {
                *(float2*)&C[o0] = r0;
                *(float2*)&C[o1] = r1;
            }
            if (Chi) {
                uint32_t h, l;
                splitpk(r0.x, r0.y, h, l);
                *(uint32_t*)&Chi[o0] = h; *(uint32_t*)&Clo[o0] = l;
                splitpk(r1.x, r1.y, h, l);
                *(uint32_t*)&Chi[o1] = h; *(uint32_t*)&Clo[o1] = l;
            }
        }
    }
}

// ---------------- mma.sync flash attention (scale = 1/H) ----------------
// 64 queries x 1 head per CTA, 4 warps (16 q-rows each). KV tiles of 64.
// QK: 3-pass split-bf16; softmax in registers; P re-packed in regs; PV: 3-pass.
#define FAPAD 72
#define FQHI 0
#define FQLO 9216
#define FKHI 18432
#define FKLO 27648
#define FVHI 36864
#define FVLO 46080
#define FLASH_SMEM 55296

__global__ void __launch_bounds__(128) flash_mma_kernel(
    const __nv_bfloat16* __restrict__ Qh, const __nv_bfloat16* __restrict__ Ql,
    const __nv_bfloat16* __restrict__ Kh, const __nv_bfloat16* __restrict__ Kl,
    const __nv_bfloat16* __restrict__ Vh, const __nv_bfloat16* __restrict__ Vl,
    float* __restrict__ O,
    __nv_bfloat16* __restrict__ Ohi, __nv_bfloat16* __restrict__ Olo) {
    extern __shared__ char smem[];
    uint32_t sb = smem_u32(smem);
    __nv_bfloat16* sQh = (__nv_bfloat16*)(smem + FQHI);
    __nv_bfloat16* sQl = (__nv_bfloat16*)(smem + FQLO);
    __nv_bfloat16* sKh = (__nv_bfloat16*)(smem + FKHI);
    __nv_bfloat16* sKl = (__nv_bfloat16*)(smem + FKLO);
    __nv_bfloat16* sVh = (__nv_bfloat16*)(smem + FVHI);
    __nv_bfloat16* sVl = (__nv_bfloat16*)(smem + FVLO);

    int tid = threadIdx.x, wid = tid >> 5, lane = tid & 31;
    int wm = wid * 16;
    int g = lane >> 2, tq = lane & 3;
    int qb = blockIdx.x, h = blockIdx.y, b = blockIdx.z;
    size_t baseQ  = ((size_t)b * Sq + (size_t)qb * 64) * Dq + h * DHq;
    size_t baseKV = (size_t)b * Sq * Dq + h * DHq;

    // Load Q tile (64x64, hi/lo)
    #pragma unroll
    for (int p = 0; p < 4; p++) {
        int e = tid + p * 128;
        int r = e >> 3, c8 = (e & 7) * 8;
        size_t go = baseQ + (size_t)r * Dq + c8;
        *(uint4*)&sQh[r * FAPAD + c8] = *(const uint4*)&Qh[go];
        *(uint4*)&sQl[r * FAPAD + c8] = *(const uint4*)&Ql[go];
    }

    float oacc[8][4];
    #pragma unroll
    for (int j = 0; j < 8; j++)
        #pragma unroll
        for (int q = 0; q < 4; q++) oacc[j][q] = 0.0f;
    float mr0 = -1e30f, mr1 = -1e30f, lr0 = 0.0f, lr1 = 0.0f;

    // ldmatrix lane-address components
    uint32_t aQ = (uint32_t)(((wm + (lane & 15)) * FAPAD + ((lane >> 4) << 3)) * 2);
    uint32_t bK = (uint32_t)(((lane & 7) * FAPAD + (((lane >> 3) & 1) << 3)) * 2);
    uint32_t bV = (uint32_t)(((lane & 15) * FAPAD) * 2);

    for (int kb = 0; kb < 16; kb++) {
        __syncthreads();
        #pragma unroll
        for (int p = 0; p < 4; p++) {
            int e = tid + p * 128;
            int r = e >> 3, c8 = (e & 7) * 8;
            size_t go = baseKV + (size_t)(kb * 64 + r) * Dq + c8;
            *(uint4*)&sKh[r * FAPAD + c8] = *(const uint4*)&Kh[go];
            *(uint4*)&sKl[r * FAPAD + c8] = *(const uint4*)&Kl[go];
            *(uint4*)&sVh[r * FAPAD + c8] = *(const uint4*)&Vh[go];
            *(uint4*)&sVl[r * FAPAD + c8] = *(const uint4*)&Vl[go];
        }
        __syncthreads();

        // S = Q @ K^T (3-pass split)
        float sacc[8][4];
        #pragma unroll
        for (int j = 0; j < 8; j++)
            #pragma unroll
            for (int q = 0; q < 4; q++) sacc[j][q] = 0.0f;

        #pragma unroll
        for (int ks = 0; ks < 4; ks++) {
            uint32_t ah[4], al[4];
            ldsm_x4(ah, sb + FQHI + aQ + ks * 32);
            ldsm_x4(al, sb + FQLO + aQ + ks * 32);
            #pragma unroll
            for (int na = 0; na < 8; na++) {
                uint32_t bh[2], bl[2];
                uint32_t off = bK + (uint32_t)(na * 8 * FAPAD * 2) + ks * 32;
                ldsm_x2(bh, sb + FKHI + off);
                ldsm_x2(bl, sb + FKLO + off);
                mma16816(sacc[na], ah, bh);
                mma16816(sacc[na], al, bh);
                mma16816(sacc[na], ah, bl);
            }
        }

        // Register softmax (rows g and g+8; quad = lanes sharing g)
        float rmax0 = -1e30f, rmax1 = -1e30f;
        #pragma unroll
        for (int j = 0; j < 8; j++) {
            sacc[j][0] *= 0.125f; sacc[j][1] *= 0.125f;
            sacc[j][2] *= 0.125f; sacc[j][3] *= 0.125f;
            rmax0 = fmaxf(rmax0, fmaxf(sacc[j][0], sacc[j][1]));
            rmax1 = fmaxf(rmax1, fmaxf(sacc[j][2], sacc[j][3]));
        }
        rmax0 = fmaxf(rmax0, __shfl_xor_sync(0xffffffffu, rmax0, 1));
        rmax0 = fmaxf(rmax0, __shfl_xor_sync(0xffffffffu, rmax0, 2));
        rmax1 = fmaxf(rmax1, __shfl_xor_sync(0xffffffffu, rmax1, 1));
        rmax1 = fmaxf(rmax1, __shfl_xor_sync(0xffffffffu, rmax1, 2));
        float mn0 = fmaxf(mr0, rmax0), mn1 = fmaxf(mr1, rmax1);
        float al0 = __expf(mr0 - mn0), al1 = __expf(mr1 - mn1);
        float sum0 = 0.0f, sum1 = 0.0f;
        #pragma unroll
        for (int j = 0; j < 8; j++) {
            sacc[j][0] = __expf(sacc[j][0] - mn0);
            sacc[j][1] = __expf(sacc[j][1] - mn0);
            sacc[j][2] = __expf(sacc[j][2] - mn1);
            sacc[j][3] = __expf(sacc[j][3] - mn1);
            sum0 += sacc[j][0] + sacc[j][1];
            sum1 += sacc[j][2] + sacc[j][3];
        }
        sum0 += __shfl_xor_sync(0xffffffffu, sum0, 1);
        sum0 += __shfl_xor_sync(0xffffffffu, sum0, 2);
        sum1 += __shfl_xor_sync(0xffffffffu, sum1, 1);
        sum1 += __shfl_xor_sync(0xffffffffu, sum1, 2);
        lr0 = lr0 * al0 + sum0; mr0 = mn0;
        lr1 = lr1 * al1 + sum1; mr1 = mn1;

        #pragma unroll
        for (int j = 0; j < 8; j++) {
            oacc[j][0] *= al0; oacc[j][1] *= al0;
            oacc[j][2] *= al1; oacc[j][3] *= al1;
        }

        // Re-pack P (C layout) into A fragments, split hi/lo
        uint32_t ph[4][4], pl[4][4];
        #pragma unroll
        for (int k2 = 0; k2 < 4; k2++) {
            splitpk(sacc[2*k2][0],   sacc[2*k2][1],   ph[k2][0], pl[k2][0]);
            splitpk(sacc[2*k2][2],   sacc[2*k2][3],   ph[k2][1], pl[k2][1]);
            splitpk(sacc[2*k2+1][0], sacc[2*k2+1][1], ph[k2][2], pl[k2][2]);
            splitpk(sacc[2*k2+1][2], sacc[2*k2+1][3], ph[k2][3], pl[k2][3]);
        }

        // O += P @ V (3-pass split; V via ldmatrix.trans on [kv][dh])
        #pragma unroll
        for (int k2 = 0; k2 < 4; k2++) {
            #pragma unroll
            for (int na = 0; na < 8; na++) {
                uint32_t bvh[2], bvl[2];
                uint32_t off = bV + (uint32_t)((k2 * 16 * FAPAD + na * 8) * 2);
                ldsm_x2t(bvh, sb + FVHI + off);
                ldsm_x2t(bvl, sb + FVLO + off);
                mma16816(oacc[na], ph[k2], bvh);
                mma16816(oacc[na], pl[k2], bvh);
                mma16816(oacc[na], ph[k2], bvl);
            }
        }
    }

    // Final normalize + store
    float il0 = 1.0f / lr0, il1 = 1.0f / lr1;
    int row0 = wm + g, row1 = wm + g + 8;
    #pragma unroll
    for (int na = 0; na < 8; na++) {
        int col = na * 8 + tq * 2;
        float v00 = oacc[na][0] * il0, v01 = oacc[na][1] * il0;
        float v10 = oacc[na][2] * il1, v11 = oacc[na][3] * il1;
        size_t o0 = baseQ + (size_t)row0 * Dq + col;
        size_t o1 = baseQ + (size_t)row1 * Dq + col;
        if (O) {
            *(float2*)&O[o0] = make_float2(v00, v01);
            *(float2*)&O[o1] = make_float2(v10, v11);
        }
        if (Ohi) {
            uint32_t hh, ll;
            splitpk(v00, v01, hh, ll);
            *(uint32_t*)&Ohi[o0] = hh; *(uint32_t*)&Olo[o0] = ll;
            splitpk(v10, v11, hh, ll);
            *(uint32_t*)&Ohi[o1] = hh; *(uint32_t*)&Olo[o1] = ll;
        }
    }
}

// ---------------- launcher ----------------
extern "C" void kernel_launch(void* const* d_in, const int* in_sizes, int n_in,
                              void* d_out, int out_size) {
    const float* in0   = (const float*)d_in[0];
    const float* in1   = (const float*)d_in[1];
    const float* Wraw[8] = {
        (const float*)d_in[2],  (const float*)d_in[3],  (const float*)d_in[4],
        (const float*)d_in[5],  (const float*)d_in[8],  (const float*)d_in[9],
        (const float*)d_in[10], (const float*)d_in[11]
    };
    const float* ge = (const float*)d_in[6];
    const float* be = (const float*)d_in[7];
    const float* gd = (const float*)d_in[12];
    const float* bd = (const float*)d_in[13];
    float* out = (float*)d_out;

    float *E, *DI, *Sb, *I, *EO;
    __nv_bfloat16 *Ahi, *Alo, *Qhi, *Qlo, *Khi, *Klo, *Vhi, *Vlo, *EOhi, *EOlo, *Whi, *Wlo;
    cudaGetSymbolAddress((void**)&E,    g_E);
    cudaGetSymbolAddress((void**)&DI,   g_DI);
    cudaGetSymbolAddress((void**)&Sb,   g_S);
    cudaGetSymbolAddress((void**)&I,    g_I);
    cudaGetSymbolAddress((void**)&EO,   g_EO);
    cudaGetSymbolAddress((void**)&Ahi,  g_Ahi);
    cudaGetSymbolAddress((void**)&Alo,  g_Alo);
    cudaGetSymbolAddress((void**)&Qhi,  g_Qhi);
    cudaGetSymbolAddress((void**)&Qlo,  g_Qlo);
    cudaGetSymbolAddress((void**)&Khi,  g_Khi);
    cudaGetSymbolAddress((void**)&Klo,  g_Klo);
    cudaGetSymbolAddress((void**)&Vhi,  g_Vhi);
    cudaGetSymbolAddress((void**)&Vlo,  g_Vlo);
    cudaGetSymbolAddress((void**)&EOhi, g_EOhi);
    cudaGetSymbolAddress((void**)&EOlo, g_EOlo);
    cudaGetSymbolAddress((void**)&Whi,  g_Wthi);
    cudaGetSymbolAddress((void**)&Wlo,  g_Wtlo);

    cudaFuncSetAttribute(gemm_mma_kernel,  cudaFuncAttributeMaxDynamicSharedMemorySize, GEMM_SMEM);
    cudaFuncSetAttribute(flash_mma_kernel, cudaFuncAttributeMaxDynamicSharedMemorySize, FLASH_SMEM);

    dim3 ggrid(Dq / 64, BSr / 128);       // (8, 64)
    dim3 fgrid(Sq / 64, Hq, Bq);          // (16, 8, 8)
    const int WSZ = Dq * Dq;

    for (int w = 0; w < 8; w++)
        cvt_wt_kernel<<<WSZ / 256, 256>>>(Wraw[w], Whi + w * WSZ, Wlo + w * WSZ);

    // ---- Encoder ----
    add_pos_kernel<<<BSD / 256, 256>>>(in0, E, Ahi, Alo);
    gemm_mma_kernel<<<ggrid, 256, GEMM_SMEM>>>(Ahi, Alo, Whi + 0 * WSZ, Wlo + 0 * WSZ, nullptr, nullptr, Qhi, Qlo);
    gemm_mma_kernel<<<ggrid, 256, GEMM_SMEM>>>(Ahi, Alo, Whi + 1 * WSZ, Wlo + 1 * WSZ, nullptr, nullptr, Khi, Klo);
    gemm_mma_kernel<<<ggrid, 256, GEMM_SMEM>>>(Ahi, Alo, Whi + 2 * WSZ, Wlo + 2 * WSZ, nullptr, nullptr, Vhi, Vlo);
    flash_mma_kernel<<<fgrid, 128, FLASH_SMEM>>>(Qhi, Qlo, Khi, Klo, Vhi, Vlo, Sb, nullptr, nullptr);
    ln_add_kernel<<<BSr, 256>>>(Sb, ge, be, E, 1.0f, I, Ahi, Alo);
    gemm_mma_kernel<<<ggrid, 256, GEMM_SMEM>>>(Ahi, Alo, Whi + 3 * WSZ, Wlo + 3 * WSZ, E, EO, EOhi, EOlo);

    // ---- Decoder ----
    add_pos_kernel<<<BSD / 256, 256>>>(in1, DI, Ahi, Alo);
    gemm_mma_kernel<<<ggrid, 256, GEMM_SMEM>>>(Ahi, Alo, Whi + 4 * WSZ, Wlo + 4 * WSZ, nullptr, nullptr, Qhi, Qlo);
    gemm_mma_kernel<<<ggrid, 256, GEMM_SMEM>>>(Ahi, Alo, Whi + 5 * WSZ, Wlo + 5 * WSZ, nullptr, nullptr, Khi, Klo);
    gemm_mma_kernel<<<ggrid, 256, GEMM_SMEM>>>(Ahi, Alo, Whi + 6 * WSZ, Wlo + 6 * WSZ, nullptr, nullptr, Vhi, Vlo);
    flash_mma_kernel<<<fgrid, 128, FLASH_SMEM>>>(Qhi, Qlo, Khi, Klo, Vhi, Vlo, Sb, nullptr, nullptr);
    ln_add_kernel<<<BSr, 256>>>(Sb, gd, bd, DI, 2.0f, I, Qhi, Qlo);   // i2 (hi/lo unused)
    flash_mma_kernel<<<fgrid, 128, FLASH_SMEM>>>(EOhi, EOlo, EOhi, EOlo, EOhi, EOlo,
                                                 nullptr, Ahi, Alo);   // eda -> bf16 only
    gemm_mma_kernel<<<ggrid, 256, GEMM_SMEM>>>(Ahi, Alo, Whi + 7 * WSZ, Wlo + 7 * WSZ, I, out, nullptr, nullptr);
}